// round 16
// baseline (speedup 1.0000x reference)
#include <cuda_runtime.h>
#include <cuda_fp16.h>
#include <stdint.h>
#include <math.h>

#define NCAM 4
#define EMB  256
#define NH   8
#define DHD  32
#define CINC 64
#define FFD  1024
#define BB   2
#define HW   9216      // 96*96
#define NPIX 18432     // BB*HW
#define NTOK 73728     // NPIX*NCAM

// ---------------- scratch (device globals; no allocation allowed) -----------
__device__ float  g_X [NTOK * EMB];                  // fp32 residual stream
__device__ __half g_Xh[NTOK * EMB];                  // fp16 copy for GEMM A
// union: QKV fp16 (113MB) | H fp16 (151MB)
__device__ __align__(1024) unsigned char g_U[(size_t)NTOK * FFD * 2];
__device__ __half g_SA[NTOK * EMB];
__device__ __half g_R [NTOK * EMB];                  // raw GEMM out (pre-residual)
__device__ __half g_FG[NTOK * CINC];
// packed fp16 weights: wp | layer{wqkv, wo, w1, w2} x2
#define WP_N     (EMB * CINC)
#define WL_SZ    (3*EMB*EMB + EMB*EMB + FFD*EMB + EMB*FFD)   // 786432
#define W_TOTAL  (WP_N + 2 * WL_SZ)
__device__ __half g_W16[W_TOTAL];
// merged head weights: rows 0-255 = Wp, rows 256-1023 = Wc = Wqkv0 @ Wp
__device__ __half g_Whead[1024 * CINC];
__device__ float  g_bhead[1024];

// ================= helpers ===================================================
__device__ __forceinline__ uint32_t smem_u32(const void* p) {
    uint32_t a;
    asm("{ .reg .u64 t; cvta.to.shared.u64 t, %1; cvt.u32.u64 %0, t; }" : "=r"(a) : "l"(p));
    return a;
}
#define LDSM_X4(r0, r1, r2, r3, a)                                                  \
    asm volatile("ldmatrix.sync.aligned.m8n8.x4.shared.b16 {%0,%1,%2,%3}, [%4];"    \
        : "=r"(r0), "=r"(r1), "=r"(r2), "=r"(r3) : "r"(a))
#define MMA16816(ac, ar, b0, b1)                                                    \
    asm volatile("mma.sync.aligned.m16n8k16.row.col.f32.f16.f16.f32 "               \
        "{%0,%1,%2,%3},{%4,%5,%6,%7},{%8,%9},{%0,%1,%2,%3};"                        \
        : "+f"((ac)[0]), "+f"((ac)[1]), "+f"((ac)[2]), "+f"((ac)[3])                \
        : "r"((ar)[0]), "r"((ar)[1]), "r"((ar)[2]), "r"((ar)[3]), "r"(b0), "r"(b1))
#define CPASYNC16(dst, src)                                                         \
    asm volatile("cp.async.cg.shared.global [%0], [%1], 16;" :: "r"(dst), "l"(src))
#define CPCOMMIT() asm volatile("cp.async.commit_group;" ::: "memory")

// ================ 1. batched weight conversion (single launch) ================
__global__ void convert_all(const float* __restrict__ Wp, const float* __restrict__ Wqkv,
                            const float* __restrict__ Wo, const float* __restrict__ W1,
                            const float* __restrict__ W2, __half* __restrict__ o) {
    int i = blockIdx.x * 256 + threadIdx.x;
    if (i >= W_TOTAL) return;
    float v;
    if (i < WP_N) {
        v = Wp[i];
    } else {
        int j = i - WP_N;
        int l = j / WL_SZ, of = j % WL_SZ;
        if (of < 196608)      v = Wqkv[(size_t)l * 196608 + of];
        else if (of < 262144) v = Wo[(size_t)l * 65536 + (of - 196608)];
        else if (of < 524288) v = W1[(size_t)l * 262144 + (of - 262144)];
        else                  v = W2[(size_t)l * 262144 + (of - 524288)];
    }
    o[i] = __float2half(v);
}

// ================ 1b. build merged head weights ===============================
__global__ void make_head(const float* __restrict__ Wqkv, const float* __restrict__ Wp,
                          const float* __restrict__ bqkv, const float* __restrict__ bp,
                          __half* __restrict__ Wh, float* __restrict__ bh) {
    int row = blockIdx.x;          // 0..1023
    int c   = threadIdx.x;         // 0..63
    if (row < 256) {
        Wh[row * CINC + c] = __float2half(Wp[row * CINC + c]);
        if (c == 0) bh[row] = bp[row];
        return;
    }
    int qr = row - 256;
    const float* wr = Wqkv + (size_t)qr * EMB;
    float s = 0.f;
    for (int k = 0; k < EMB; k++) s += wr[k] * Wp[k * CINC + c];
    Wh[row * CINC + c] = __float2half(s);
    if (c == 0) {
        float b = bqkv[qr];
        for (int k = 0; k < EMB; k++) b += wr[k] * bp[k];
        bh[row] = b;
    }
}

// ================ 2. gather features -> [NTOK, 64] fp16 =======================
__global__ void gather_feat(const float* __restrict__ f, __half* __restrict__ o) {
    __shared__ float s[64][65];
    int blk  = blockIdx.x;
    int hwb  = blk % (HW / 64);
    int camb = blk / (HW / 64);
    const float* base = f + ((size_t)camb * CINC) * HW + hwb * 64;
    for (int i = threadIdx.x; i < 64 * 64; i += 256) {
        int c = i >> 6, hwi = i & 63;
        s[c][hwi] = base[(size_t)c * HW + hwi];
    }
    __syncthreads();
    int cam = camb / BB, b = camb % BB;
    for (int i = threadIdx.x; i < 64 * 64; i += 256) {
        int hwi = i >> 6, c = i & 63;
        int t = (b * HW + hwb * 64 + hwi) * NCAM + cam;
        o[(size_t)t * CINC + c] = __float2half(s[c][hwi]);
    }
}

// ================ 3. fp16 tensor-core TN GEMM (R9 proven core) ================
// C[M,N] = act(A[M,K] @ W[N,K]^T + bias); BM=128, BN=128, BK=64, 3 stages,
// 8 warps 2x4, warp tile 64x32, 2 CTAs/SM.
#define STG_BYTES 32768          // A 16KB + W 16KB per stage
#define SMEM_REQ  (3 * STG_BYTES)

__device__ __forceinline__ void load_stage(uint32_t st, const __half* A,
                                           const __half* W, int K) {
    int tid = threadIdx.x;
#pragma unroll
    for (int i = 0; i < 4; i++) {
        int idx = tid + i * 256;          // 1024 chunks each for A and W
        int r = idx >> 3, c = idx & 7;
        uint32_t off = (uint32_t)(r * 128 + c * 16);
        uint32_t sw = off ^ ((off >> 3) & 0x70);
        CPASYNC16(st + sw,         (const void*)(A + (size_t)r * K + c * 8));
        CPASYNC16(st + 16384 + sw, (const void*)(W + (size_t)r * K + c * 8));
    }
    CPCOMMIT();
}

__global__ void __launch_bounds__(256, 2) gemm_f16(
    const __half* __restrict__ A, const __half* __restrict__ W,
    const float* __restrict__ bias,
    float* __restrict__ Cf, __half* __restrict__ Ch,
    int N, int K, int relu)
{
    extern __shared__ char smem[];
    uint32_t sb = smem_u32(smem);
    int tid = threadIdx.x, lane = tid & 31, wid = tid >> 5;
    int wm = wid >> 2, wn = wid & 3;          // 2 x 4 warp grid
    int m0 = blockIdx.y * 128, n0 = blockIdx.x * 128;

    const __half* Ab = A + (size_t)m0 * K;
    const __half* Wb = W + (size_t)n0 * K;

    uint32_t baseA[4], xorA[4], baseB[2], xorB[2];
#pragma unroll
    for (int mt = 0; mt < 4; mt++) {
        int r = wm * 64 + mt * 16 + (lane & 7) + ((lane >> 3) & 1) * 8;
        baseA[mt] = r * 128;
        xorA[mt] = (r & 7) * 16;
    }
#pragma unroll
    for (int g = 0; g < 2; g++) {
        int r = wn * 32 + g * 16 + (lane & 7) + ((lane >> 4) & 1) * 8;
        baseB[g] = 16384 + r * 128;
        xorB[g] = (r & 7) * 16;
    }
    int kA = ((lane >> 4) & 1) * 16;
    int kB = ((lane >> 3) & 1) * 16;

    float acc[4][4][4];
#pragma unroll
    for (int i = 0; i < 4; i++)
#pragma unroll
        for (int j = 0; j < 4; j++)
#pragma unroll
            for (int c = 0; c < 4; c++) acc[i][j][c] = 0.f;

    int nk = K >> 6;
    load_stage(sb, Ab, Wb, K);
    if (nk > 1) load_stage(sb + STG_BYTES, Ab + 64, Wb + 64, K);

    for (int kb = 0; kb < nk; kb++) {
        if (kb == nk - 1) asm volatile("cp.async.wait_group 0;" ::: "memory");
        else              asm volatile("cp.async.wait_group 1;" ::: "memory");
        __syncthreads();
        if (kb + 2 < nk)
            load_stage(sb + ((kb + 2) % 3) * STG_BYTES,
                       Ab + (kb + 2) * 64, Wb + (kb + 2) * 64, K);
        uint32_t st = sb + (kb % 3) * STG_BYTES;
#pragma unroll
        for (int ks = 0; ks < 4; ks++) {
            int kb0 = ks * 32;
            uint32_t b[2][4];
#pragma unroll
            for (int g = 0; g < 2; g++) {
                uint32_t ofs = baseB[g] + ((kb0 + kB) ^ xorB[g]);
                LDSM_X4(b[g][0], b[g][1], b[g][2], b[g][3], st + ofs);
            }
#pragma unroll
            for (int mt = 0; mt < 4; mt++) {
                uint32_t a[4];
                uint32_t ofs = baseA[mt] + ((kb0 + kA) ^ xorA[mt]);
                LDSM_X4(a[0], a[1], a[2], a[3], st + ofs);
#pragma unroll
                for (int nt = 0; nt < 4; nt++) {
                    int g = nt >> 1, pr = (nt & 1) * 2;
                    MMA16816(acc[mt][nt], a, b[g][pr], b[g][pr + 1]);
                }
            }
        }
    }

    int mw = m0 + wm * 64 + (lane >> 2);
    int nw = n0 + wn * 32 + (lane & 3) * 2;
#pragma unroll
    for (int mt = 0; mt < 4; mt++) {
#pragma unroll
        for (int nt = 0; nt < 4; nt++) {
            int n = nw + nt * 8;
            float2 bv = *(const float2*)(bias + n);
#pragma unroll
            for (int half = 0; half < 2; half++) {
                size_t m = (size_t)(mw + mt * 16 + half * 8);
                float v0 = acc[mt][nt][half * 2 + 0] + bv.x;
                float v1 = acc[mt][nt][half * 2 + 1] + bv.y;
                if (relu) { v0 = fmaxf(v0, 0.f); v1 = fmaxf(v1, 0.f); }
                if (Cf) *(float2*)(Cf + m * N + n) = make_float2(v0, v1);
                if (Ch) *(__half2*)(Ch + m * N + n) = __floats2half2_rn(v0, v1);
            }
        }
    }
}

// ================ 3b. merged head GEMM: K=64, N=1024, BM=256, 512 threads =====
// cols 0-255 -> X fp32 (input projection); cols 256-1023 -> QKV fp16 (layer-0)
// 16 warps in 4x4 grid of 64x32 tiles; single 48KB stage (A 32KB + W 16KB).
#define GH_SMEM 49152

__global__ void __launch_bounds__(512, 1) gemm_head(
    const __half* __restrict__ A, const __half* __restrict__ W,
    const float* __restrict__ bias,
    float* __restrict__ X, __half* __restrict__ QKV)
{
    extern __shared__ char smem[];
    uint32_t sb = smem_u32(smem);
    int tid = threadIdx.x, lane = tid & 31, wid = tid >> 5;
    int wm = wid >> 2, wn = wid & 3;          // 4 x 4 warp grid, 64x32 tiles
    int m0 = blockIdx.y * 256, n0 = blockIdx.x * 128;
    const int K = CINC;

    const __half* Ab = A + (size_t)m0 * K;
    const __half* Wb = W + (size_t)n0 * K;

    // load: A 256 rows (2048 chunks), W 128 rows (1024 chunks); 512 threads
#pragma unroll
    for (int i = 0; i < 4; i++) {
        int idx = tid + i * 512;
        int r = idx >> 3, c = idx & 7;
        uint32_t off = (uint32_t)(r * 128 + c * 16);
        uint32_t sw = off ^ ((off >> 3) & 0x70);
        CPASYNC16(sb + sw, (const void*)(Ab + (size_t)r * K + c * 8));
    }
#pragma unroll
    for (int i = 0; i < 2; i++) {
        int idx = tid + i * 512;
        int r = idx >> 3, c = idx & 7;
        uint32_t off = (uint32_t)(r * 128 + c * 16);
        uint32_t sw = off ^ ((off >> 3) & 0x70);
        CPASYNC16(sb + 32768 + sw, (const void*)(Wb + (size_t)r * K + c * 8));
    }
    CPCOMMIT();

    uint32_t baseA[4], xorA[4], baseB[2], xorB[2];
#pragma unroll
    for (int mt = 0; mt < 4; mt++) {
        int r = wm * 64 + mt * 16 + (lane & 7) + ((lane >> 3) & 1) * 8;
        baseA[mt] = r * 128;
        xorA[mt] = (r & 7) * 16;
    }
#pragma unroll
    for (int g = 0; g < 2; g++) {
        int r = wn * 32 + g * 16 + (lane & 7) + ((lane >> 4) & 1) * 8;
        baseB[g] = 32768 + r * 128;
        xorB[g] = (r & 7) * 16;
    }
    int kA = ((lane >> 4) & 1) * 16;
    int kB = ((lane >> 3) & 1) * 16;

    float acc[4][4][4];
#pragma unroll
    for (int i = 0; i < 4; i++)
#pragma unroll
        for (int j = 0; j < 4; j++)
#pragma unroll
            for (int c = 0; c < 4; c++) acc[i][j][c] = 0.f;

    asm volatile("cp.async.wait_group 0;" ::: "memory");
    __syncthreads();
#pragma unroll
    for (int ks = 0; ks < 4; ks++) {
        int kb0 = ks * 32;
        uint32_t b[2][4];
#pragma unroll
        for (int g = 0; g < 2; g++) {
            uint32_t ofs = baseB[g] + ((kb0 + kB) ^ xorB[g]);
            LDSM_X4(b[g][0], b[g][1], b[g][2], b[g][3], sb + ofs);
        }
#pragma unroll
        for (int mt = 0; mt < 4; mt++) {
            uint32_t a[4];
            uint32_t ofs = baseA[mt] + ((kb0 + kA) ^ xorA[mt]);
            LDSM_X4(a[0], a[1], a[2], a[3], sb + ofs);
#pragma unroll
            for (int nt = 0; nt < 4; nt++) {
                int g = nt >> 1, pr = (nt & 1) * 2;
                MMA16816(acc[mt][nt], a, b[g][pr], b[g][pr + 1]);
            }
        }
    }

    int mw = m0 + wm * 64 + (lane >> 2);
    int nw = n0 + wn * 32 + (lane & 3) * 2;
    int toX = (n0 < 256);
#pragma unroll
    for (int mt = 0; mt < 4; mt++) {
#pragma unroll
        for (int nt = 0; nt < 4; nt++) {
            int n = nw + nt * 8;
            float2 bv = *(const float2*)(bias + n);
#pragma unroll
            for (int half = 0; half < 2; half++) {
                size_t m = (size_t)(mw + mt * 16 + half * 8);
                float v0 = acc[mt][nt][half * 2 + 0] + bv.x;
                float v1 = acc[mt][nt][half * 2 + 1] + bv.y;
                if (toX)
                    *(float2*)(X + m * EMB + n) = make_float2(v0, v1);
                else
                    *(__half2*)(QKV + m * (3 * EMB) + (n - 256)) = __floats2half2_rn(v0, v1);
            }
        }
    }
}

// ================ 4. attention (S=4), half2-vectorized ========================
__global__ void attn_kernel(const __half* __restrict__ qkv, __half* __restrict__ sa) {
    int wid  = threadIdx.x >> 5;
    int lane = threadIdx.x & 31;
    int pix  = blockIdx.x * 2 + (wid >> 2);
    int col  = (wid & 3) * 64 + lane * 2;    // embed column in [0,256)
    size_t base = (size_t)pix * NCAM * 768 + col;

    float2 q[4], k[4], v[4];
#pragma unroll
    for (int c = 0; c < 4; c++) {
        q[c] = __half22float2(*(const __half2*)(qkv + base + (size_t)c * 768));
        k[c] = __half22float2(*(const __half2*)(qkv + base + (size_t)c * 768 + 256));
        v[c] = __half22float2(*(const __half2*)(qkv + base + (size_t)c * 768 + 512));
    }
    const float scale = 0.17677669529663687f;
    float s[4][4];
#pragma unroll
    for (int i = 0; i < 4; i++)
#pragma unroll
        for (int j = 0; j < 4; j++) {
            float p = q[i].x * k[j].x + q[i].y * k[j].y;
#pragma unroll
            for (int o = 8; o > 0; o >>= 1) p += __shfl_xor_sync(0xffffffffu, p, o);
            s[i][j] = p * scale;
        }
    size_t ob = (size_t)pix * NCAM * EMB + col;
#pragma unroll
    for (int i = 0; i < 4; i++) {
        float mx = fmaxf(fmaxf(s[i][0], s[i][1]), fmaxf(s[i][2], s[i][3]));
        float e0 = __expf(s[i][0] - mx), e1 = __expf(s[i][1] - mx);
        float e2 = __expf(s[i][2] - mx), e3 = __expf(s[i][3] - mx);
        float inv = 1.0f / (e0 + e1 + e2 + e3);
        float ox = (e0 * v[0].x + e1 * v[1].x + e2 * v[2].x + e3 * v[3].x) * inv;
        float oy = (e0 * v[0].y + e1 * v[1].y + e2 * v[2].y + e3 * v[3].y) * inv;
        *(__half2*)(sa + ob + (size_t)i * EMB) = __floats2half2_rn(ox, oy);
    }
}

// ================ 5. fused residual-add + LayerNorm ===========================
__global__ void ln_add(const __half* __restrict__ raw, float* __restrict__ x,
                       __half* __restrict__ xh,
                       const float* __restrict__ g, const float* __restrict__ be,
                       int writeX) {
    int row  = blockIdx.x * 8 + (threadIdx.x >> 5);
    int lane = threadIdx.x & 31;
    float* p = x + (size_t)row * EMB;
    const __half* rp = raw + (size_t)row * EMB;
    float vals[8];
    float sum = 0.f;
#pragma unroll
    for (int j = 0; j < 8; j++) {
        int e = lane + 32 * j;
        vals[j] = p[e] + __half2float(rp[e]);
        sum += vals[j];
    }
#pragma unroll
    for (int o = 16; o > 0; o >>= 1) sum += __shfl_xor_sync(0xffffffffu, sum, o);
    float mu = sum * (1.0f / EMB);
    float vs = 0.f;
#pragma unroll
    for (int j = 0; j < 8; j++) { float d = vals[j] - mu; vs += d * d; }
#pragma unroll
    for (int o = 16; o > 0; o >>= 1) vs += __shfl_xor_sync(0xffffffffu, vs, o);
    float inv = rsqrtf(vs * (1.0f / EMB) + 1e-5f);
#pragma unroll
    for (int j = 0; j < 8; j++) {
        int e = lane + 32 * j;
        float y = (vals[j] - mu) * inv * g[e] + be[e];
        if (writeX) p[e] = y;
        xh[(size_t)row * EMB + e] = __float2half(y);
    }
}

// ================ 6. fused mean-over-cams + output 1x1 conv ===================
__global__ void outconv(const __half* __restrict__ xh, const float* __restrict__ Wout,
                        const float* __restrict__ bout, float* __restrict__ out) {
    __shared__ float4 fs[16][64];
    float* fsf = (float*)fs;
    int p0 = blockIdx.x * 16;
    for (int idx = threadIdx.x; idx < 16 * 256; idx += 256) {
        int pi = idx >> 8, e = idx & 255;
        size_t b = ((size_t)(p0 + pi) * NCAM) * EMB + e;
        float v = __half2float(xh[b]) + __half2float(xh[b + EMB]) +
                  __half2float(xh[b + 2 * EMB]) + __half2float(xh[b + 3 * EMB]);
        fsf[pi * 256 + e] = 0.25f * v;
    }
    __syncthreads();
    int c = threadIdx.x & 63, pg = threadIdx.x >> 6;
    float acc[4] = {0.f, 0.f, 0.f, 0.f};
    const float4* Wr = (const float4*)(Wout + (size_t)c * EMB);
#pragma unroll 8
    for (int eq = 0; eq < 64; eq++) {
        float4 w = Wr[eq];
#pragma unroll
        for (int pi = 0; pi < 4; pi++) {
            float4 f = fs[pg * 4 + pi][eq];
            acc[pi] += w.x * f.x + w.y * f.y + w.z * f.z + w.w * f.w;
        }
    }
    float bc = bout[c];
#pragma unroll
    for (int pi = 0; pi < 4; pi++) {
        int p = p0 + pg * 4 + pi;
        int b = p / HW, hw = p % HW;
        out[((size_t)(b * CINC + c)) * HW + hw] = acc[pi] + bc;
    }
}

// ================ launch ======================================================
extern "C" void kernel_launch(void* const* d_in, const int* in_sizes, int n_in,
                              void* d_out, int out_size) {
    const float* features = (const float*)d_in[0];
    const float* Wp   = (const float*)d_in[1];
    const float* bp   = (const float*)d_in[2];
    const float* Wqkv = (const float*)d_in[3];
    const float* bqkv = (const float*)d_in[4];
    const float* Wo   = (const float*)d_in[5];
    const float* bo   = (const float*)d_in[6];
    const float* W1   = (const float*)d_in[7];
    const float* b1   = (const float*)d_in[8];
    const float* W2   = (const float*)d_in[9];
    const float* b2   = (const float*)d_in[10];
    const float* g1   = (const float*)d_in[11];
    const float* be1  = (const float*)d_in[12];
    const float* g2   = (const float*)d_in[13];
    const float* be2  = (const float*)d_in[14];
    const float* Wout = (const float*)d_in[15];
    const float* bout = (const float*)d_in[16];
    float* out = (float*)d_out;

    float* X;
    unsigned char* U;
    __half *Xh, *SA, *R, *FG, *W16, *Wh;
    float* bh;
    cudaGetSymbolAddress((void**)&X,   g_X);
    cudaGetSymbolAddress((void**)&U,   g_U);
    cudaGetSymbolAddress((void**)&Xh,  g_Xh);
    cudaGetSymbolAddress((void**)&SA,  g_SA);
    cudaGetSymbolAddress((void**)&R,   g_R);
    cudaGetSymbolAddress((void**)&FG,  g_FG);
    cudaGetSymbolAddress((void**)&W16, g_W16);
    cudaGetSymbolAddress((void**)&Wh,  g_Whead);
    cudaGetSymbolAddress((void**)&bh,  g_bhead);
    __half* QKV = (__half*)U;           // live: qkv gemm -> attn
    __half* Hf  = (__half*)U;           // live: ffn1 -> ffn2

    cudaFuncSetAttribute(gemm_f16,  cudaFuncAttributeMaxDynamicSharedMemorySize, SMEM_REQ);
    cudaFuncSetAttribute(gemm_head, cudaFuncAttributeMaxDynamicSharedMemorySize, GH_SMEM);

    convert_all<<<(W_TOTAL + 255) / 256, 256>>>(Wp, Wqkv, Wo, W1, W2, W16);
    make_head<<<1024, CINC>>>(Wqkv, Wp, bqkv, bp, Wh, bh);
    gather_feat<<<NCAM * BB * (HW / 64), 256>>>(features, FG);
    // merged head: X (input proj) + QKV layer-0, one launch, K=64, BM=256
    gemm_head<<<dim3(8, NTOK / 256), 512, GH_SMEM>>>(FG, Wh, bh, X, QKV);

    for (int i = 0; i < 2; i++) {
        size_t lb = WP_N + (size_t)i * WL_SZ;
        const float* bq  = bqkv + (size_t)i * 3 * EMB;
        const float* boi = bo   + (size_t)i * EMB;
        const float* b1i = b1   + (size_t)i * FFD;
        const float* b2i = b2   + (size_t)i * EMB;

        // QKV projection: layer 0 already produced by gemm_head
        if (i == 1)
            gemm_f16<<<dim3(6, NTOK / 128), 256, SMEM_REQ>>>(Xh, W16 + lb, bq,
                                                             nullptr, QKV, 3 * EMB, EMB, 0);
        attn_kernel<<<NPIX / 2, 256>>>(QKV, SA);
        // Wo projection -> raw R
        gemm_f16<<<dim3(2, NTOK / 128), 256, SMEM_REQ>>>(SA, W16 + lb + 196608, boi,
                                                         nullptr, R, EMB, EMB, 0);
        ln_add<<<NTOK / 8, 256>>>(R, X, Xh, g1 + (size_t)i * EMB, be1 + (size_t)i * EMB, 1);
        // FFN1 (relu)
        gemm_f16<<<dim3(8, NTOK / 128), 256, SMEM_REQ>>>(Xh, W16 + lb + 262144, b1i,
                                                         nullptr, Hf, FFD, EMB, 1);
        // FFN2 -> raw R
        gemm_f16<<<dim3(2, NTOK / 128), 256, SMEM_REQ>>>(Hf, W16 + lb + 524288, b2i,
                                                         nullptr, R, EMB, FFD, 0);
        ln_add<<<NTOK / 8, 256>>>(R, X, Xh, g2 + (size_t)i * EMB, be2 + (size_t)i * EMB,
                                  i == 0 ? 1 : 0);
    }

    outconv<<<NPIX / 16, 256>>>(Xh, Wout, bout, out);
}

// round 17
// speedup vs baseline: 1.0267x; 1.0267x over previous
#include <cuda_runtime.h>
#include <cuda_fp16.h>
#include <stdint.h>
#include <math.h>

#define NCAM 4
#define EMB  256
#define NH   8
#define DHD  32
#define CINC 64
#define FFD  1024
#define BB   2
#define HW   9216      // 96*96
#define NPIX 18432     // BB*HW
#define NTOK 73728     // NPIX*NCAM

// ---------------- scratch (device globals; no allocation allowed) -----------
__device__ float  g_X [NTOK * EMB];                  // fp32 residual stream
__device__ __half g_Xh[NTOK * EMB];                  // fp16 copy for GEMM A
// union: QKV fp16 (113MB) | H fp16 (151MB)
__device__ __align__(1024) unsigned char g_U[(size_t)NTOK * FFD * 2];
__device__ __half g_SA[NTOK * EMB];
__device__ __half g_R [NTOK * EMB];                  // raw GEMM out (pre-residual)
__device__ __half g_FG[NTOK * CINC];
// packed fp16 weights: wp | layer{wqkv, wo, w1, w2} x2
#define WP_N     (EMB * CINC)
#define WL_SZ    (3*EMB*EMB + EMB*EMB + FFD*EMB + EMB*FFD)   // 786432
#define W_TOTAL  (WP_N + 2 * WL_SZ)
__device__ __half g_W16[W_TOTAL];
// merged head weights: rows 0-255 = Wp, rows 256-1023 = Wc = Wqkv0 @ Wp
__device__ __half g_Whead[1024 * CINC];
__device__ float  g_bhead[1024];

// ================= helpers ===================================================
__device__ __forceinline__ uint32_t smem_u32(const void* p) {
    uint32_t a;
    asm("{ .reg .u64 t; cvta.to.shared.u64 t, %1; cvt.u32.u64 %0, t; }" : "=r"(a) : "l"(p));
    return a;
}
#define LDSM_X4(r0, r1, r2, r3, a)                                                  \
    asm volatile("ldmatrix.sync.aligned.m8n8.x4.shared.b16 {%0,%1,%2,%3}, [%4];"    \
        : "=r"(r0), "=r"(r1), "=r"(r2), "=r"(r3) : "r"(a))
#define MMA16816(ac, ar, b0, b1)                                                    \
    asm volatile("mma.sync.aligned.m16n8k16.row.col.f32.f16.f16.f32 "               \
        "{%0,%1,%2,%3},{%4,%5,%6,%7},{%8,%9},{%0,%1,%2,%3};"                        \
        : "+f"((ac)[0]), "+f"((ac)[1]), "+f"((ac)[2]), "+f"((ac)[3])                \
        : "r"((ar)[0]), "r"((ar)[1]), "r"((ar)[2]), "r"((ar)[3]), "r"(b0), "r"(b1))
#define CPASYNC16(dst, src)                                                         \
    asm volatile("cp.async.cg.shared.global [%0], [%1], 16;" :: "r"(dst), "l"(src))
#define CPCOMMIT() asm volatile("cp.async.commit_group;" ::: "memory")

// ================ 1. batched weight conversion (single launch) ================
__global__ void convert_all(const float* __restrict__ Wp, const float* __restrict__ Wqkv,
                            const float* __restrict__ Wo, const float* __restrict__ W1,
                            const float* __restrict__ W2, __half* __restrict__ o) {
    int i = blockIdx.x * 256 + threadIdx.x;
    if (i >= W_TOTAL) return;
    float v;
    if (i < WP_N) {
        v = Wp[i];
    } else {
        int j = i - WP_N;
        int l = j / WL_SZ, of = j % WL_SZ;
        if (of < 196608)      v = Wqkv[(size_t)l * 196608 + of];
        else if (of < 262144) v = Wo[(size_t)l * 65536 + (of - 196608)];
        else if (of < 524288) v = W1[(size_t)l * 262144 + (of - 262144)];
        else                  v = W2[(size_t)l * 262144 + (of - 524288)];
    }
    o[i] = __float2half(v);
}

// ================ 1b. build merged head weights ===============================
__global__ void make_head(const float* __restrict__ Wqkv, const float* __restrict__ Wp,
                          const float* __restrict__ bqkv, const float* __restrict__ bp,
                          __half* __restrict__ Wh, float* __restrict__ bh) {
    int row = blockIdx.x;          // 0..1023
    int c   = threadIdx.x;         // 0..63
    if (row < 256) {
        Wh[row * CINC + c] = __float2half(Wp[row * CINC + c]);
        if (c == 0) bh[row] = bp[row];
        return;
    }
    int qr = row - 256;
    const float* wr = Wqkv + (size_t)qr * EMB;
    float s = 0.f;
    for (int k = 0; k < EMB; k++) s += wr[k] * Wp[k * CINC + c];
    Wh[row * CINC + c] = __float2half(s);
    if (c == 0) {
        float b = bqkv[qr];
        for (int k = 0; k < EMB; k++) b += wr[k] * bp[k];
        bh[row] = b;
    }
}

// ================ 2. gather features -> [NTOK, 64] fp16 =======================
__global__ void gather_feat(const float* __restrict__ f, __half* __restrict__ o) {
    __shared__ float s[64][65];
    int blk  = blockIdx.x;
    int hwb  = blk % (HW / 64);
    int camb = blk / (HW / 64);
    const float* base = f + ((size_t)camb * CINC) * HW + hwb * 64;
    for (int i = threadIdx.x; i < 64 * 64; i += 256) {
        int c = i >> 6, hwi = i & 63;
        s[c][hwi] = base[(size_t)c * HW + hwi];
    }
    __syncthreads();
    int cam = camb / BB, b = camb % BB;
    for (int i = threadIdx.x; i < 64 * 64; i += 256) {
        int hwi = i >> 6, c = i & 63;
        int t = (b * HW + hwb * 64 + hwi) * NCAM + cam;
        o[(size_t)t * CINC + c] = __float2half(s[c][hwi]);
    }
}

// ================ 3. fp16 tensor-core TN GEMM (R9 proven core) ================
// C[M,N] = act(A[M,K] @ W[N,K]^T + bias); BM=128, BN=128, BK=64, 3 stages,
// 8 warps 2x4, warp tile 64x32, 2 CTAs/SM.
#define STG_BYTES 32768          // A 16KB + W 16KB per stage
#define SMEM_REQ  (3 * STG_BYTES)

__device__ __forceinline__ void load_stage(uint32_t st, const __half* A,
                                           const __half* W, int K) {
    int tid = threadIdx.x;
#pragma unroll
    for (int i = 0; i < 4; i++) {
        int idx = tid + i * 256;          // 1024 chunks each for A and W
        int r = idx >> 3, c = idx & 7;
        uint32_t off = (uint32_t)(r * 128 + c * 16);
        uint32_t sw = off ^ ((off >> 3) & 0x70);
        CPASYNC16(st + sw,         (const void*)(A + (size_t)r * K + c * 8));
        CPASYNC16(st + 16384 + sw, (const void*)(W + (size_t)r * K + c * 8));
    }
    CPCOMMIT();
}

__global__ void __launch_bounds__(256, 2) gemm_f16(
    const __half* __restrict__ A, const __half* __restrict__ W,
    const float* __restrict__ bias,
    float* __restrict__ Cf, __half* __restrict__ Ch,
    int N, int K, int relu)
{
    extern __shared__ char smem[];
    uint32_t sb = smem_u32(smem);
    int tid = threadIdx.x, lane = tid & 31, wid = tid >> 5;
    int wm = wid >> 2, wn = wid & 3;          // 2 x 4 warp grid
    int m0 = blockIdx.y * 128, n0 = blockIdx.x * 128;

    const __half* Ab = A + (size_t)m0 * K;
    const __half* Wb = W + (size_t)n0 * K;

    uint32_t baseA[4], xorA[4], baseB[2], xorB[2];
#pragma unroll
    for (int mt = 0; mt < 4; mt++) {
        int r = wm * 64 + mt * 16 + (lane & 7) + ((lane >> 3) & 1) * 8;
        baseA[mt] = r * 128;
        xorA[mt] = (r & 7) * 16;
    }
#pragma unroll
    for (int g = 0; g < 2; g++) {
        int r = wn * 32 + g * 16 + (lane & 7) + ((lane >> 4) & 1) * 8;
        baseB[g] = 16384 + r * 128;
        xorB[g] = (r & 7) * 16;
    }
    int kA = ((lane >> 4) & 1) * 16;
    int kB = ((lane >> 3) & 1) * 16;

    float acc[4][4][4];
#pragma unroll
    for (int i = 0; i < 4; i++)
#pragma unroll
        for (int j = 0; j < 4; j++)
#pragma unroll
            for (int c = 0; c < 4; c++) acc[i][j][c] = 0.f;

    int nk = K >> 6;
    load_stage(sb, Ab, Wb, K);
    if (nk > 1) load_stage(sb + STG_BYTES, Ab + 64, Wb + 64, K);

    for (int kb = 0; kb < nk; kb++) {
        if (kb == nk - 1) asm volatile("cp.async.wait_group 0;" ::: "memory");
        else              asm volatile("cp.async.wait_group 1;" ::: "memory");
        __syncthreads();
        if (kb + 2 < nk)
            load_stage(sb + ((kb + 2) % 3) * STG_BYTES,
                       Ab + (kb + 2) * 64, Wb + (kb + 2) * 64, K);
        uint32_t st = sb + (kb % 3) * STG_BYTES;
#pragma unroll
        for (int ks = 0; ks < 4; ks++) {
            int kb0 = ks * 32;
            uint32_t b[2][4];
#pragma unroll
            for (int g = 0; g < 2; g++) {
                uint32_t ofs = baseB[g] + ((kb0 + kB) ^ xorB[g]);
                LDSM_X4(b[g][0], b[g][1], b[g][2], b[g][3], st + ofs);
            }
#pragma unroll
            for (int mt = 0; mt < 4; mt++) {
                uint32_t a[4];
                uint32_t ofs = baseA[mt] + ((kb0 + kA) ^ xorA[mt]);
                LDSM_X4(a[0], a[1], a[2], a[3], st + ofs);
#pragma unroll
                for (int nt = 0; nt < 4; nt++) {
                    int g = nt >> 1, pr = (nt & 1) * 2;
                    MMA16816(acc[mt][nt], a, b[g][pr], b[g][pr + 1]);
                }
            }
        }
    }

    int mw = m0 + wm * 64 + (lane >> 2);
    int nw = n0 + wn * 32 + (lane & 3) * 2;
#pragma unroll
    for (int mt = 0; mt < 4; mt++) {
#pragma unroll
        for (int nt = 0; nt < 4; nt++) {
            int n = nw + nt * 8;
            float2 bv = *(const float2*)(bias + n);
#pragma unroll
            for (int half = 0; half < 2; half++) {
                size_t m = (size_t)(mw + mt * 16 + half * 8);
                float v0 = acc[mt][nt][half * 2 + 0] + bv.x;
                float v1 = acc[mt][nt][half * 2 + 1] + bv.y;
                if (relu) { v0 = fmaxf(v0, 0.f); v1 = fmaxf(v1, 0.f); }
                if (Cf) *(float2*)(Cf + m * N + n) = make_float2(v0, v1);
                if (Ch) *(__half2*)(Ch + m * N + n) = __floats2half2_rn(v0, v1);
            }
        }
    }
}

// ================ 3b. merged head GEMM (R15 proven): K=64, N=1024, BM=128 =====
// cols 0-255 -> X fp32 (input projection); cols 256-1023 -> QKV fp16 (layer-0)
__global__ void __launch_bounds__(256, 2) gemm_head(
    const __half* __restrict__ A, const __half* __restrict__ W,
    const float* __restrict__ bias,
    float* __restrict__ X, __half* __restrict__ QKV)
{
    extern __shared__ char smem[];
    uint32_t sb = smem_u32(smem);
    int tid = threadIdx.x, lane = tid & 31, wid = tid >> 5;
    int wm = wid >> 2, wn = wid & 3;
    int m0 = blockIdx.y * 128, n0 = blockIdx.x * 128;
    const int K = CINC;

    const __half* Ab = A + (size_t)m0 * K;
    const __half* Wb = W + (size_t)n0 * K;

    uint32_t baseA[4], xorA[4], baseB[2], xorB[2];
#pragma unroll
    for (int mt = 0; mt < 4; mt++) {
        int r = wm * 64 + mt * 16 + (lane & 7) + ((lane >> 3) & 1) * 8;
        baseA[mt] = r * 128;
        xorA[mt] = (r & 7) * 16;
    }
#pragma unroll
    for (int g = 0; g < 2; g++) {
        int r = wn * 32 + g * 16 + (lane & 7) + ((lane >> 4) & 1) * 8;
        baseB[g] = 16384 + r * 128;
        xorB[g] = (r & 7) * 16;
    }
    int kA = ((lane >> 4) & 1) * 16;
    int kB = ((lane >> 3) & 1) * 16;

    float acc[4][4][4];
#pragma unroll
    for (int i = 0; i < 4; i++)
#pragma unroll
        for (int j = 0; j < 4; j++)
#pragma unroll
            for (int c = 0; c < 4; c++) acc[i][j][c] = 0.f;

    load_stage(sb, Ab, Wb, K);
    asm volatile("cp.async.wait_group 0;" ::: "memory");
    __syncthreads();
#pragma unroll
    for (int ks = 0; ks < 4; ks++) {
        int kb0 = ks * 32;
        uint32_t b[2][4];
#pragma unroll
        for (int g = 0; g < 2; g++) {
            uint32_t ofs = baseB[g] + ((kb0 + kB) ^ xorB[g]);
            LDSM_X4(b[g][0], b[g][1], b[g][2], b[g][3], sb + ofs);
        }
#pragma unroll
        for (int mt = 0; mt < 4; mt++) {
            uint32_t a[4];
            uint32_t ofs = baseA[mt] + ((kb0 + kA) ^ xorA[mt]);
            LDSM_X4(a[0], a[1], a[2], a[3], sb + ofs);
#pragma unroll
            for (int nt = 0; nt < 4; nt++) {
                int g = nt >> 1, pr = (nt & 1) * 2;
                MMA16816(acc[mt][nt], a, b[g][pr], b[g][pr + 1]);
            }
        }
    }

    int mw = m0 + wm * 64 + (lane >> 2);
    int nw = n0 + wn * 32 + (lane & 3) * 2;
    int toX = (n0 < 256);
#pragma unroll
    for (int mt = 0; mt < 4; mt++) {
#pragma unroll
        for (int nt = 0; nt < 4; nt++) {
            int n = nw + nt * 8;
            float2 bv = *(const float2*)(bias + n);
#pragma unroll
            for (int half = 0; half < 2; half++) {
                size_t m = (size_t)(mw + mt * 16 + half * 8);
                float v0 = acc[mt][nt][half * 2 + 0] + bv.x;
                float v1 = acc[mt][nt][half * 2 + 1] + bv.y;
                if (toX)
                    *(float2*)(X + m * EMB + n) = make_float2(v0, v1);
                else
                    *(__half2*)(QKV + m * (3 * EMB) + (n - 256)) = __floats2half2_rn(v0, v1);
            }
        }
    }
}

// ================ 4. attention (S=4), half2-vectorized ========================
__global__ void attn_kernel(const __half* __restrict__ qkv, __half* __restrict__ sa) {
    int wid  = threadIdx.x >> 5;
    int lane = threadIdx.x & 31;
    int pix  = blockIdx.x * 2 + (wid >> 2);
    int col  = (wid & 3) * 64 + lane * 2;    // embed column in [0,256)
    size_t base = (size_t)pix * NCAM * 768 + col;

    float2 q[4], k[4], v[4];
#pragma unroll
    for (int c = 0; c < 4; c++) {
        q[c] = __half22float2(*(const __half2*)(qkv + base + (size_t)c * 768));
        k[c] = __half22float2(*(const __half2*)(qkv + base + (size_t)c * 768 + 256));
        v[c] = __half22float2(*(const __half2*)(qkv + base + (size_t)c * 768 + 512));
    }
    const float scale = 0.17677669529663687f;
    float s[4][4];
#pragma unroll
    for (int i = 0; i < 4; i++)
#pragma unroll
        for (int j = 0; j < 4; j++) {
            float p = q[i].x * k[j].x + q[i].y * k[j].y;
#pragma unroll
            for (int o = 8; o > 0; o >>= 1) p += __shfl_xor_sync(0xffffffffu, p, o);
            s[i][j] = p * scale;
        }
    size_t ob = (size_t)pix * NCAM * EMB + col;
#pragma unroll
    for (int i = 0; i < 4; i++) {
        float mx = fmaxf(fmaxf(s[i][0], s[i][1]), fmaxf(s[i][2], s[i][3]));
        float e0 = __expf(s[i][0] - mx), e1 = __expf(s[i][1] - mx);
        float e2 = __expf(s[i][2] - mx), e3 = __expf(s[i][3] - mx);
        float inv = 1.0f / (e0 + e1 + e2 + e3);
        float ox = (e0 * v[0].x + e1 * v[1].x + e2 * v[2].x + e3 * v[3].x) * inv;
        float oy = (e0 * v[0].y + e1 * v[1].y + e2 * v[2].y + e3 * v[3].y) * inv;
        *(__half2*)(sa + ob + (size_t)i * EMB) = __floats2half2_rn(ox, oy);
    }
}

// ================ 5. fused residual-add + LayerNorm ===========================
__global__ void ln_add(const __half* __restrict__ raw, float* __restrict__ x,
                       __half* __restrict__ xh,
                       const float* __restrict__ g, const float* __restrict__ be,
                       int writeX) {
    int row  = blockIdx.x * 8 + (threadIdx.x >> 5);
    int lane = threadIdx.x & 31;
    float* p = x + (size_t)row * EMB;
    const __half* rp = raw + (size_t)row * EMB;
    float vals[8];
    float sum = 0.f;
#pragma unroll
    for (int j = 0; j < 8; j++) {
        int e = lane + 32 * j;
        vals[j] = p[e] + __half2float(rp[e]);
        sum += vals[j];
    }
#pragma unroll
    for (int o = 16; o > 0; o >>= 1) sum += __shfl_xor_sync(0xffffffffu, sum, o);
    float mu = sum * (1.0f / EMB);
    float vs = 0.f;
#pragma unroll
    for (int j = 0; j < 8; j++) { float d = vals[j] - mu; vs += d * d; }
#pragma unroll
    for (int o = 16; o > 0; o >>= 1) vs += __shfl_xor_sync(0xffffffffu, vs, o);
    float inv = rsqrtf(vs * (1.0f / EMB) + 1e-5f);
#pragma unroll
    for (int j = 0; j < 8; j++) {
        int e = lane + 32 * j;
        float y = (vals[j] - mu) * inv * g[e] + be[e];
        if (writeX) p[e] = y;
        xh[(size_t)row * EMB + e] = __float2half(y);
    }
}

// ================ 6. fused final-LN + mean-over-cams + output conv ============
// For 16 pixels/block: LN(X + R) per token row (fp32), mean over 4 cams in
// registers, then 1x1 conv with Wout.
__global__ void ln_outconv(const __half* __restrict__ R, const float* __restrict__ X,
                           const float* __restrict__ g, const float* __restrict__ be,
                           const float* __restrict__ Wout, const float* __restrict__ bout,
                           float* __restrict__ out) {
    __shared__ float4 fs[16][64];
    float* fsf = (float*)fs;
    int p0 = blockIdx.x * 16;
    int lane = threadIdx.x & 31, wid = threadIdx.x >> 5;

    // warp wid handles pixels wid*2, wid*2+1 (4 cam-rows each)
#pragma unroll
    for (int pl = 0; pl < 2; pl++) {
        int pi = wid * 2 + pl;
        float accm[8];
#pragma unroll
        for (int j = 0; j < 8; j++) accm[j] = 0.f;
#pragma unroll
        for (int cam = 0; cam < 4; cam++) {
            size_t m = ((size_t)(p0 + pi) * NCAM + cam);
            const float* p = X + m * EMB;
            const __half* rp = R + m * EMB;
            float vals[8];
            float sum = 0.f;
#pragma unroll
            for (int j = 0; j < 8; j++) {
                int e = lane + 32 * j;
                vals[j] = p[e] + __half2float(rp[e]);
                sum += vals[j];
            }
#pragma unroll
            for (int o = 16; o > 0; o >>= 1) sum += __shfl_xor_sync(0xffffffffu, sum, o);
            float mu = sum * (1.0f / EMB);
            float vs = 0.f;
#pragma unroll
            for (int j = 0; j < 8; j++) { float d = vals[j] - mu; vs += d * d; }
#pragma unroll
            for (int o = 16; o > 0; o >>= 1) vs += __shfl_xor_sync(0xffffffffu, vs, o);
            float inv = rsqrtf(vs * (1.0f / EMB) + 1e-5f);
#pragma unroll
            for (int j = 0; j < 8; j++) {
                int e = lane + 32 * j;
                accm[j] += (vals[j] - mu) * inv * g[e] + be[e];
            }
        }
#pragma unroll
        for (int j = 0; j < 8; j++)
            fsf[pi * 256 + lane + 32 * j] = 0.25f * accm[j];
    }
    __syncthreads();

    int c = threadIdx.x & 63, pg = threadIdx.x >> 6;
    float acc[4] = {0.f, 0.f, 0.f, 0.f};
    const float4* Wr = (const float4*)(Wout + (size_t)c * EMB);
#pragma unroll 8
    for (int eq = 0; eq < 64; eq++) {
        float4 w = Wr[eq];
#pragma unroll
        for (int pi = 0; pi < 4; pi++) {
            float4 f = fs[pg * 4 + pi][eq];
            acc[pi] += w.x * f.x + w.y * f.y + w.z * f.z + w.w * f.w;
        }
    }
    float bc = bout[c];
#pragma unroll
    for (int pi = 0; pi < 4; pi++) {
        int p = p0 + pg * 4 + pi;
        int b = p / HW, hw = p % HW;
        out[((size_t)(b * CINC + c)) * HW + hw] = acc[pi] + bc;
    }
}

// ================ launch ======================================================
extern "C" void kernel_launch(void* const* d_in, const int* in_sizes, int n_in,
                              void* d_out, int out_size) {
    const float* features = (const float*)d_in[0];
    const float* Wp   = (const float*)d_in[1];
    const float* bp   = (const float*)d_in[2];
    const float* Wqkv = (const float*)d_in[3];
    const float* bqkv = (const float*)d_in[4];
    const float* Wo   = (const float*)d_in[5];
    const float* bo   = (const float*)d_in[6];
    const float* W1   = (const float*)d_in[7];
    const float* b1   = (const float*)d_in[8];
    const float* W2   = (const float*)d_in[9];
    const float* b2   = (const float*)d_in[10];
    const float* g1   = (const float*)d_in[11];
    const float* be1  = (const float*)d_in[12];
    const float* g2   = (const float*)d_in[13];
    const float* be2  = (const float*)d_in[14];
    const float* Wout = (const float*)d_in[15];
    const float* bout = (const float*)d_in[16];
    float* out = (float*)d_out;

    float* X;
    unsigned char* U;
    __half *Xh, *SA, *R, *FG, *W16, *Wh;
    float* bh;
    cudaGetSymbolAddress((void**)&X,   g_X);
    cudaGetSymbolAddress((void**)&U,   g_U);
    cudaGetSymbolAddress((void**)&Xh,  g_Xh);
    cudaGetSymbolAddress((void**)&SA,  g_SA);
    cudaGetSymbolAddress((void**)&R,   g_R);
    cudaGetSymbolAddress((void**)&FG,  g_FG);
    cudaGetSymbolAddress((void**)&W16, g_W16);
    cudaGetSymbolAddress((void**)&Wh,  g_Whead);
    cudaGetSymbolAddress((void**)&bh,  g_bhead);
    __half* QKV = (__half*)U;           // live: qkv gemm -> attn
    __half* Hf  = (__half*)U;           // live: ffn1 -> ffn2

    cudaFuncSetAttribute(gemm_f16,  cudaFuncAttributeMaxDynamicSharedMemorySize, SMEM_REQ);
    cudaFuncSetAttribute(gemm_head, cudaFuncAttributeMaxDynamicSharedMemorySize, SMEM_REQ);

    convert_all<<<(W_TOTAL + 255) / 256, 256>>>(Wp, Wqkv, Wo, W1, W2, W16);
    make_head<<<1024, CINC>>>(Wqkv, Wp, bqkv, bp, Wh, bh);
    gather_feat<<<NCAM * BB * (HW / 64), 256>>>(features, FG);
    // merged head: X (input proj) + QKV layer-0, one launch, K=64 (R15 config)
    gemm_head<<<dim3(8, NTOK / 128), 256, SMEM_REQ>>>(FG, Wh, bh, X, QKV);

    for (int i = 0; i < 2; i++) {
        size_t lb = WP_N + (size_t)i * WL_SZ;
        const float* bq  = bqkv + (size_t)i * 3 * EMB;
        const float* boi = bo   + (size_t)i * EMB;
        const float* b1i = b1   + (size_t)i * FFD;
        const float* b2i = b2   + (size_t)i * EMB;

        // QKV projection: layer 0 already produced by gemm_head
        if (i == 1)
            gemm_f16<<<dim3(6, NTOK / 128), 256, SMEM_REQ>>>(Xh, W16 + lb, bq,
                                                             nullptr, QKV, 3 * EMB, EMB, 0);
        attn_kernel<<<NPIX / 2, 256>>>(QKV, SA);
        // Wo projection -> raw R
        gemm_f16<<<dim3(2, NTOK / 128), 256, SMEM_REQ>>>(SA, W16 + lb + 196608, boi,
                                                         nullptr, R, EMB, EMB, 0);
        ln_add<<<NTOK / 8, 256>>>(R, X, Xh, g1 + (size_t)i * EMB, be1 + (size_t)i * EMB, 1);
        // FFN1 (relu)
        gemm_f16<<<dim3(8, NTOK / 128), 256, SMEM_REQ>>>(Xh, W16 + lb + 262144, b1i,
                                                         nullptr, Hf, FFD, EMB, 1);
        // FFN2 -> raw R
        gemm_f16<<<dim3(2, NTOK / 128), 256, SMEM_REQ>>>(Hf, W16 + lb + 524288, b2i,
                                                         nullptr, R, EMB, FFD, 0);
        if (i == 0)
            ln_add<<<NTOK / 8, 256>>>(R, X, Xh, g2, be2, 1);
    }

    // final LN (layer-1 LN2) fused with mean-over-cams + output conv
    ln_outconv<<<NPIX / 16, 256>>>(R, X, g2 + EMB, be2 + EMB, Wout, bout, out);
}